// round 12
// baseline (speedup 1.0000x reference)
#include <cuda_runtime.h>
#include <cuda_bf16.h>
#include <math.h>

// Problem constants (fixed shapes per reference)
#define NN 50000
#define EE 600000
// HID = 128, H = 4, C = 32

// ---------------- scratch (device globals; no allocation allowed) ----------
__device__ float g_h0[NN * 128];     // x @ W_gcn
__device__ float g_h[NN * 128];      // GCN aggregation / post-ReLU features
__device__ float g_q[NN * 128];
__device__ float g_k[NN * 128];
__device__ float g_v[NN * 128];
__device__ float g_dinv[NN];
__device__ int   g_deg[NN];
__device__ float g_alpha[EE * 4];    // per-edge per-head logits, then exp()
__device__ float g_m[NN * 4];        // per-target per-head max
__device__ float g_denom[NN * 4];    // per-target per-head sum of exp

// ---------------- helpers ---------------------------------------------------
__device__ __forceinline__ void red_add_v4(float* addr, float4 v) {
    asm volatile("red.global.add.v4.f32 [%0], {%1,%2,%3,%4};"
                 :: "l"(addr), "f"(v.x), "f"(v.y), "f"(v.z), "f"(v.w)
                 : "memory");
}

__device__ __forceinline__ void atomicMaxF(float* addr, float v) {
    // float ordering == int ordering for non-negative, reversed uint for negative
    if (v >= 0.0f) atomicMax((int*)addr, __float_as_int(v));
    else           atomicMin((unsigned int*)addr, __float_as_uint(v));
}

// ---------------- init: zero accumulators, deg=1 (self loop), m=-inf -------
__global__ void k_init() {
    int i = blockIdx.x * blockDim.x + threadIdx.x;
    if (i < NN * 128) g_h[i] = 0.0f;
    if (i < NN * 4) {
        g_m[i] = __int_as_float(0xFF800000);  // -inf
        g_denom[i] = 0.0f;
    }
    if (i < NN) g_deg[i] = 1;
}

// ---------------- GEMM: Y[n,128] = X[n,128] @ W[128,128] (+bias) ------------
// W fully resident in smem (64KB) + 64-row X tile (32KB). 256 threads.
// Thread (rid=tid/32, cid=tid%32) computes rows rid*8..rid*8+7, cols cid*4..cid*4+3.
__global__ __launch_bounds__(256) void gemm128(
    const float* __restrict__ X, const float* __restrict__ W,
    const float* __restrict__ bias, float* __restrict__ Y, int n)
{
    extern __shared__ float sm[];
    float* Ws = sm;                 // 128*128
    float* Xs = sm + 128 * 128;     // 64*128
    const int tid = threadIdx.x;
    const int row0 = blockIdx.x * 64;

    float4* Ws4 = (float4*)Ws;
    const float4* W4 = (const float4*)W;
    #pragma unroll
    for (int i = tid; i < 128 * 32; i += 256) Ws4[i] = W4[i];

    float4* Xs4 = (float4*)Xs;
    const float4* X4 = (const float4*)X;
    #pragma unroll
    for (int i = tid; i < 64 * 32; i += 256) {
        int r = i >> 5;
        int row = row0 + r;
        Xs4[i] = (row < n) ? X4[row * 32 + (i & 31)] : make_float4(0.f, 0.f, 0.f, 0.f);
    }
    __syncthreads();

    const int cid = tid & 31;
    const int rid = tid >> 5;
    float acc[8][4];
    #pragma unroll
    for (int r = 0; r < 8; r++)
        #pragma unroll
        for (int j = 0; j < 4; j++) acc[r][j] = 0.0f;

    #pragma unroll 4
    for (int k = 0; k < 128; k++) {
        float4 wv = Ws4[k * 32 + cid];
        #pragma unroll
        for (int r = 0; r < 8; r++) {
            float xv = Xs[(rid * 8 + r) * 128 + k];  // broadcast within warp
            acc[r][0] = fmaf(xv, wv.x, acc[r][0]);
            acc[r][1] = fmaf(xv, wv.y, acc[r][1]);
            acc[r][2] = fmaf(xv, wv.z, acc[r][2]);
            acc[r][3] = fmaf(xv, wv.w, acc[r][3]);
        }
    }

    float4 bv = bias ? ((const float4*)bias)[cid] : make_float4(0.f, 0.f, 0.f, 0.f);
    #pragma unroll
    for (int r = 0; r < 8; r++) {
        int row = row0 + rid * 8 + r;
        if (row < n) {
            float4 o;
            o.x = acc[r][0] + bv.x; o.y = acc[r][1] + bv.y;
            o.z = acc[r][2] + bv.z; o.w = acc[r][3] + bv.w;
            ((float4*)Y)[row * 32 + cid] = o;
        }
    }
}

// ---------------- degree count ----------------------------------------------
__global__ void k_deg(const int* __restrict__ tgt) {
    int e = blockIdx.x * blockDim.x + threadIdx.x;
    if (e < EE) atomicAdd(&g_deg[tgt[e]], 1);
}

__global__ void k_dinv() {
    int i = blockIdx.x * blockDim.x + threadIdx.x;
    if (i < NN) g_dinv[i] = rsqrtf((float)g_deg[i]);   // deg >= 1 always
}

// ---------------- GCN edge scatter: h[t] += h0[s] * dinv[s]*dinv[t] ---------
__global__ void k_gcn_scatter(const int* __restrict__ src, const int* __restrict__ tgt) {
    int gt = blockIdx.x * blockDim.x + threadIdx.x;
    int e = gt >> 5;
    if (e >= EE) return;
    int lane = threadIdx.x & 31;
    int s = src[e], t = tgt[e];
    float norm = g_dinv[s] * g_dinv[t];
    float4 hv = ((const float4*)g_h0)[s * 32 + lane];
    hv.x *= norm; hv.y *= norm; hv.z *= norm; hv.w *= norm;
    red_add_v4(&g_h[t * 128 + lane * 4], hv);
}

// ---------------- self-loop + bias + ReLU ------------------------------------
__global__ void k_relu(const float* __restrict__ b_gcn) {
    int i = blockIdx.x * blockDim.x + threadIdx.x;
    if (i >= NN * 32) return;
    int node = i >> 5;
    int c = i & 31;
    float di = g_dinv[node];
    float sw = di * di;
    float4 hv = ((float4*)g_h)[i];
    float4 h0v = ((const float4*)g_h0)[i];
    float4 bv = ((const float4*)b_gcn)[c];
    hv.x = fmaxf(fmaf(h0v.x, sw, hv.x) + bv.x, 0.f);
    hv.y = fmaxf(fmaf(h0v.y, sw, hv.y) + bv.y, 0.f);
    hv.z = fmaxf(fmaf(h0v.z, sw, hv.z) + bv.z, 0.f);
    hv.w = fmaxf(fmaf(h0v.w, sw, hv.w) + bv.w, 0.f);
    ((float4*)g_h)[i] = hv;
}

// ---------------- attention logits + segment max ----------------------------
__global__ void k_alpha(const int* __restrict__ src, const int* __restrict__ tgt) {
    int gt = blockIdx.x * blockDim.x + threadIdx.x;
    int e = gt >> 5;
    if (e >= EE) return;
    int lane = threadIdx.x & 31;
    int s = src[e], t = tgt[e];
    float4 qv = ((const float4*)g_q)[t * 32 + lane];
    float4 kv = ((const float4*)g_k)[s * 32 + lane];
    float p = qv.x * kv.x + qv.y * kv.y + qv.z * kv.z + qv.w * kv.w;
    // reduce within 8-lane groups (one head = 32 cols = 8 lanes of float4)
    p += __shfl_xor_sync(0xffffffffu, p, 1);
    p += __shfl_xor_sync(0xffffffffu, p, 2);
    p += __shfl_xor_sync(0xffffffffu, p, 4);
    if ((lane & 7) == 0) {
        int hd = lane >> 3;
        float a = p * 0.17677669529663687f;   // 1/sqrt(32)
        g_alpha[e * 4 + hd] = a;
        atomicMaxF(&g_m[t * 4 + hd], a);
    }
}

// ---------------- exp(alpha - m), accumulate denom ---------------------------
__global__ void k_ea(const int* __restrict__ tgt) {
    int i = blockIdx.x * blockDim.x + threadIdx.x;
    if (i >= EE * 4) return;
    int e = i >> 2;
    int hd = i & 3;
    int t = tgt[e];
    float a = g_alpha[i];
    float mm = g_m[t * 4 + hd];
    float ev = expf(a - mm);
    g_alpha[i] = ev;
    atomicAdd(&g_denom[t * 4 + hd], ev);
}

// ---------------- attention scatter: out[t] += w * v[s] ----------------------
__global__ void k_attn_scatter(const int* __restrict__ src, const int* __restrict__ tgt,
                               float* __restrict__ out) {
    int gt = blockIdx.x * blockDim.x + threadIdx.x;
    int e = gt >> 5;
    if (e >= EE) return;
    int lane = threadIdx.x & 31;
    int s = src[e], t = tgt[e];
    float w = 0.0f;
    if (lane < 4) {
        float num = g_alpha[e * 4 + lane];
        float den = g_denom[t * 4 + lane];
        w = num / (den > 0.0f ? den : 1.0f);
    }
    float ww = __shfl_sync(0xffffffffu, w, lane >> 3);  // head = lane/8
    float4 vv = ((const float4*)g_v)[s * 32 + lane];
    vv.x *= ww; vv.y *= ww; vv.z *= ww; vv.w *= ww;
    red_add_v4(out + t * 128 + lane * 4, vv);
}

// ---------------- launch -----------------------------------------------------
extern "C" void kernel_launch(void* const* d_in, const int* in_sizes, int n_in,
                              void* d_out, int out_size) {
    const float* x  = (const float*)d_in[0];
    const int*   ei = (const int*)d_in[1];
    const int* srcE = ei;        // edge_index[0]
    const int* tgtE = ei + EE;   // edge_index[1]
    const float* Wg = (const float*)d_in[2];
    const float* bg = (const float*)d_in[3];
    const float* Wq = (const float*)d_in[4];
    const float* bq = (const float*)d_in[5];
    const float* Wk = (const float*)d_in[6];
    const float* bk = (const float*)d_in[7];
    const float* Wv = (const float*)d_in[8];
    const float* bv = (const float*)d_in[9];
    const float* Wsk = (const float*)d_in[10];
    const float* bsk = (const float*)d_in[11];
    float* out = (float*)d_out;

    void *p_h0, *p_h, *p_q, *p_k, *p_v;
    cudaGetSymbolAddress(&p_h0, g_h0);
    cudaGetSymbolAddress(&p_h,  g_h);
    cudaGetSymbolAddress(&p_q,  g_q);
    cudaGetSymbolAddress(&p_k,  g_k);
    cudaGetSymbolAddress(&p_v,  g_v);

    const int SMEM = (128 * 128 + 64 * 128) * (int)sizeof(float);  // 96KB
    cudaFuncSetAttribute(gemm128, cudaFuncAttributeMaxDynamicSharedMemorySize, SMEM);

    const int TB = 256;
    // init accumulators
    k_init<<<(NN * 128 + TB - 1) / TB, TB>>>();
    // h0 = x @ W_gcn
    gemm128<<<(NN + 63) / 64, TB, SMEM>>>(x, Wg, nullptr, (float*)p_h0, NN);
    // degrees + dinv
    k_deg<<<(EE + TB - 1) / TB, TB>>>(tgtE);
    k_dinv<<<(NN + TB - 1) / TB, TB>>>();
    // GCN scatter (1 warp / edge)
    k_gcn_scatter<<<(EE * 32 + TB - 1) / TB, TB>>>(srcE, tgtE);
    // self-loop + bias + ReLU -> g_h
    k_relu<<<(NN * 32 + TB - 1) / TB, TB>>>(bg);
    // projections
    gemm128<<<(NN + 63) / 64, TB, SMEM>>>((const float*)p_h, Wq, bq, (float*)p_q, NN);
    gemm128<<<(NN + 63) / 64, TB, SMEM>>>((const float*)p_h, Wk, bk, (float*)p_k, NN);
    gemm128<<<(NN + 63) / 64, TB, SMEM>>>((const float*)p_h, Wv, bv, (float*)p_v, NN);
    // skip connection straight into the output buffer
    gemm128<<<(NN + 63) / 64, TB, SMEM>>>((const float*)p_h, Wsk, bsk, out, NN);
    // attention
    k_alpha<<<(EE * 32 + TB - 1) / TB, TB>>>(srcE, tgtE);
    k_ea<<<(EE * 4 + TB - 1) / TB, TB>>>(tgtE);
    k_attn_scatter<<<(EE * 32 + TB - 1) / TB, TB>>>(srcE, tgtE, out);
}

// round 13
// speedup vs baseline: 1.0132x; 1.0132x over previous
#include <cuda_runtime.h>
#include <cuda_bf16.h>
#include <math.h>

// Problem constants (fixed shapes per reference)
#define NN 50000
#define EE 600000
// HID = 128, H = 4, C = 32

// ---------------- scratch (device globals; no allocation allowed) ----------
__device__ float g_h0[NN * 128];     // x @ W_gcn
__device__ float g_h[NN * 128];      // GCN aggregation / post-ReLU features
__device__ float g_q[NN * 128];
__device__ float g_k[NN * 128];
__device__ float g_v[NN * 128];
__device__ float g_att[NN * 128];    // unnormalized attention accumulation
__device__ float g_dinv[NN];
__device__ int   g_deg[NN];
__device__ float g_denom[NN * 4];    // per-target per-head sum of exp(alpha)

// ---------------- helpers ---------------------------------------------------
__device__ __forceinline__ void red_add_v4(float* addr, float4 v) {
    asm volatile("red.global.add.v4.f32 [%0], {%1,%2,%3,%4};"
                 :: "l"(addr), "f"(v.x), "f"(v.y), "f"(v.z), "f"(v.w)
                 : "memory");
}

__device__ __forceinline__ unsigned long long pack2(float lo, float hi) {
    unsigned long long d;
    asm("mov.b64 %0, {%1, %2};" : "=l"(d) : "f"(lo), "f"(hi));
    return d;
}
__device__ __forceinline__ void unpack2(unsigned long long v, float& lo, float& hi) {
    asm("mov.b64 {%0, %1}, %2;" : "=f"(lo), "=f"(hi) : "l"(v));
}
__device__ __forceinline__ void fma2(unsigned long long& acc, unsigned long long a,
                                     unsigned long long b) {
    asm("fma.rn.f32x2 %0, %1, %2, %0;" : "+l"(acc) : "l"(a), "l"(b));
}

// ---------------- init: zero accumulators, deg=1 (self loop) ----------------
__global__ void k_init() {
    int i = blockIdx.x * blockDim.x + threadIdx.x;
    if (i < NN * 128) { g_h[i] = 0.0f; g_att[i] = 0.0f; }
    if (i < NN * 4) g_denom[i] = 0.0f;
    if (i < NN) g_deg[i] = 1;
}

// ---------------- GEMM: up to 4 weight sets, shared X tile -------------------
// Y_j[n,128] = X[n,128] @ W_j[128,128] (+ b_j).  f32x2 packed FMA.
// Tile: 128 rows x 128 cols per CTA, 256 threads (8 warps).
// warp wid handles rows wid*16..wid*16+15 (8 row-pairs); lane handles cols lane*4..+3.
// X tile stored transposed in smem: XsT[k][row] so a row-pair is one LDS.64 broadcast.
__global__ __launch_bounds__(256) void gemm4(
    const float* __restrict__ X,
    const float* __restrict__ W0, const float* __restrict__ b0, float* __restrict__ Y0,
    const float* __restrict__ W1, const float* __restrict__ b1, float* __restrict__ Y1,
    const float* __restrict__ W2, const float* __restrict__ b2, float* __restrict__ Y2,
    const float* __restrict__ W3, const float* __restrict__ b3, float* __restrict__ Y3,
    int n)
{
    extern __shared__ float sm[];
    float* Ws  = sm;               // [k][col] 128*128
    float* XsT = sm + 128 * 128;   // [k][row] 128*128
    const int tid  = threadIdx.x;
    const int lane = tid & 31;
    const int wid  = tid >> 5;
    const int row0 = blockIdx.x * 128;
    const int rbase = wid * 16;

    // Fill XsT (transposed). Lanes spread over rows so smem stores are
    // conflict-free (bank = row % 32); global reads are strided but L2-resident.
    const float4* X4 = (const float4*)X;
    for (int i = tid; i < 128 * 32; i += 256) {
        int r  = i & 127;
        int c4 = i >> 7;
        int row = row0 + r;
        float4 xv = (row < n) ? X4[row * 32 + c4] : make_float4(0.f, 0.f, 0.f, 0.f);
        XsT[(c4 * 4 + 0) * 128 + r] = xv.x;
        XsT[(c4 * 4 + 1) * 128 + r] = xv.y;
        XsT[(c4 * 4 + 2) * 128 + r] = xv.z;
        XsT[(c4 * 4 + 3) * 128 + r] = xv.w;
    }

    const float* Warr[4] = {W0, W1, W2, W3};
    const float* barr[4] = {b0, b1, b2, b3};
    float*       Yarr[4] = {Y0, Y1, Y2, Y3};

    for (int wsel = 0; wsel < 4; wsel++) {
        const float* W = Warr[wsel];
        if (!W) break;
        __syncthreads();   // prior reads of Ws done (and XsT visible on first pass)
        {
            float4* Ws4 = (float4*)Ws;
            const float4* W4 = (const float4*)W;
            for (int i = tid; i < 128 * 32; i += 256) Ws4[i] = W4[i];
        }
        __syncthreads();

        unsigned long long acc[8][4];
        #pragma unroll
        for (int rp = 0; rp < 8; rp++)
            #pragma unroll
            for (int c = 0; c < 4; c++) acc[rp][c] = 0ull;

        const float4* Ws4 = (const float4*)Ws;
        #pragma unroll 4
        for (int k = 0; k < 128; k++) {
            float4 wv = Ws4[k * 32 + lane];
            unsigned long long wp0 = pack2(wv.x, wv.x);
            unsigned long long wp1 = pack2(wv.y, wv.y);
            unsigned long long wp2 = pack2(wv.z, wv.z);
            unsigned long long wp3 = pack2(wv.w, wv.w);
            const float* xrow = &XsT[k * 128 + rbase];
            #pragma unroll
            for (int rp = 0; rp < 8; rp++) {
                unsigned long long xx =
                    *reinterpret_cast<const unsigned long long*>(xrow + rp * 2);
                fma2(acc[rp][0], xx, wp0);
                fma2(acc[rp][1], xx, wp1);
                fma2(acc[rp][2], xx, wp2);
                fma2(acc[rp][3], xx, wp3);
            }
        }

        const float* b = barr[wsel];
        float4 bv = b ? ((const float4*)b)[lane] : make_float4(0.f, 0.f, 0.f, 0.f);
        float4* Y4 = (float4*)Yarr[wsel];
        #pragma unroll
        for (int rp = 0; rp < 8; rp++) {
            float lo0, hi0, lo1, hi1, lo2, hi2, lo3, hi3;
            unpack2(acc[rp][0], lo0, hi0);
            unpack2(acc[rp][1], lo1, hi1);
            unpack2(acc[rp][2], lo2, hi2);
            unpack2(acc[rp][3], lo3, hi3);
            int row = row0 + rbase + rp * 2;
            if (row < n) {
                float4 o = make_float4(lo0 + bv.x, lo1 + bv.y, lo2 + bv.z, lo3 + bv.w);
                Y4[row * 32 + lane] = o;
            }
            if (row + 1 < n) {
                float4 o = make_float4(hi0 + bv.x, hi1 + bv.y, hi2 + bv.z, hi3 + bv.w);
                Y4[(row + 1) * 32 + lane] = o;
            }
        }
    }
}

// ---------------- degree count ----------------------------------------------
__global__ void k_deg(const int* __restrict__ tgt) {
    int e = blockIdx.x * blockDim.x + threadIdx.x;
    if (e < EE) atomicAdd(&g_deg[tgt[e]], 1);
}

__global__ void k_dinv() {
    int i = blockIdx.x * blockDim.x + threadIdx.x;
    if (i < NN) g_dinv[i] = rsqrtf((float)g_deg[i]);   // deg >= 1 always
}

// ---------------- GCN edge scatter: h[t] += h0[s] * dinv[s]*dinv[t] ---------
__global__ void k_gcn_scatter(const int* __restrict__ src, const int* __restrict__ tgt) {
    int gt = blockIdx.x * blockDim.x + threadIdx.x;
    int e = gt >> 5;
    if (e >= EE) return;
    int lane = threadIdx.x & 31;
    int s = src[e], t = tgt[e];
    float norm = g_dinv[s] * g_dinv[t];
    float4 hv = ((const float4*)g_h0)[s * 32 + lane];
    hv.x *= norm; hv.y *= norm; hv.z *= norm; hv.w *= norm;
    red_add_v4(&g_h[t * 128 + lane * 4], hv);
}

// ---------------- self-loop + bias + ReLU ------------------------------------
__global__ void k_relu(const float* __restrict__ b_gcn) {
    int i = blockIdx.x * blockDim.x + threadIdx.x;
    if (i >= NN * 32) return;
    int node = i >> 5;
    int c = i & 31;
    float di = g_dinv[node];
    float sw = di * di;
    float4 hv = ((float4*)g_h)[i];
    float4 h0v = ((const float4*)g_h0)[i];
    float4 bv = ((const float4*)b_gcn)[c];
    hv.x = fmaxf(fmaf(h0v.x, sw, hv.x) + bv.x, 0.f);
    hv.y = fmaxf(fmaf(h0v.y, sw, hv.y) + bv.y, 0.f);
    hv.z = fmaxf(fmaf(h0v.z, sw, hv.z) + bv.z, 0.f);
    hv.w = fmaxf(fmaf(h0v.w, sw, hv.w) + bv.w, 0.f);
    ((float4*)g_h)[i] = hv;
}

// ---------------- fused attention edge pass ----------------------------------
// One warp per edge. Computes alpha = q[t].k[s]/sqrt(C) per head, ea = exp(alpha)
// (no max subtraction: |alpha| is O(6) here, exp can't overflow; the softmax is
// identical after normalization), scatters ea*v[s] into g_att and ea into g_denom.
__global__ void k_attn(const int* __restrict__ src, const int* __restrict__ tgt) {
    int gt = blockIdx.x * blockDim.x + threadIdx.x;
    int e = gt >> 5;
    if (e >= EE) return;
    int lane = threadIdx.x & 31;
    int s = src[e], t = tgt[e];
    float4 qv = ((const float4*)g_q)[t * 32 + lane];
    float4 kv = ((const float4*)g_k)[s * 32 + lane];
    float p = qv.x * kv.x + qv.y * kv.y + qv.z * kv.z + qv.w * kv.w;
    // reduce within 8-lane groups (one head = 32 cols = 8 lanes of float4);
    // after the 3 xors every lane in the group holds the head's dot product
    p += __shfl_xor_sync(0xffffffffu, p, 1);
    p += __shfl_xor_sync(0xffffffffu, p, 2);
    p += __shfl_xor_sync(0xffffffffu, p, 4);
    float ea = __expf(p * 0.17677669529663687f);   // 1/sqrt(32)
    if ((lane & 7) == 0) atomicAdd(&g_denom[t * 4 + (lane >> 3)], ea);
    float4 vv = ((const float4*)g_v)[s * 32 + lane];
    vv.x *= ea; vv.y *= ea; vv.z *= ea; vv.w *= ea;
    red_add_v4(&g_att[t * 128 + lane * 4], vv);
}

// ---------------- normalize + add into skip output ---------------------------
__global__ void k_combine(float* __restrict__ out) {
    int i = blockIdx.x * blockDim.x + threadIdx.x;
    if (i >= NN * 32) return;
    int node = i >> 5;
    int head = (i & 31) >> 3;
    float den = g_denom[node * 4 + head];
    float inv = (den > 0.0f) ? (1.0f / den) : 0.0f;
    float4 o = ((float4*)out)[i];
    float4 a = ((const float4*)g_att)[i];
    o.x += a.x * inv; o.y += a.y * inv;
    o.z += a.z * inv; o.w += a.w * inv;
    ((float4*)out)[i] = o;
}

// ---------------- launch -----------------------------------------------------
extern "C" void kernel_launch(void* const* d_in, const int* in_sizes, int n_in,
                              void* d_out, int out_size) {
    const float* x  = (const float*)d_in[0];
    const int*   ei = (const int*)d_in[1];
    const int* srcE = ei;        // edge_index[0]
    const int* tgtE = ei + EE;   // edge_index[1]
    const float* Wg = (const float*)d_in[2];
    const float* bg = (const float*)d_in[3];
    const float* Wq = (const float*)d_in[4];
    const float* bq = (const float*)d_in[5];
    const float* Wk = (const float*)d_in[6];
    const float* bk = (const float*)d_in[7];
    const float* Wv = (const float*)d_in[8];
    const float* bv = (const float*)d_in[9];
    const float* Wsk = (const float*)d_in[10];
    const float* bsk = (const float*)d_in[11];
    float* out = (float*)d_out;

    void *p_h0, *p_h, *p_q, *p_k, *p_v;
    cudaGetSymbolAddress(&p_h0, g_h0);
    cudaGetSymbolAddress(&p_h,  g_h);
    cudaGetSymbolAddress(&p_q,  g_q);
    cudaGetSymbolAddress(&p_k,  g_k);
    cudaGetSymbolAddress(&p_v,  g_v);

    const int SMEM = 2 * 128 * 128 * (int)sizeof(float);   // 128KB
    cudaFuncSetAttribute(gemm4, cudaFuncAttributeMaxDynamicSharedMemorySize, SMEM);

    const int TB = 256;
    const int GBLK = (NN + 127) / 128;

    // init accumulators
    k_init<<<(NN * 128 + TB - 1) / TB, TB>>>();
    // h0 = x @ W_gcn
    gemm4<<<GBLK, TB, SMEM>>>(x,
        Wg, nullptr, (float*)p_h0,
        nullptr, nullptr, nullptr,
        nullptr, nullptr, nullptr,
        nullptr, nullptr, nullptr, NN);
    // degrees + dinv
    k_deg<<<(EE + TB - 1) / TB, TB>>>(tgtE);
    k_dinv<<<(NN + TB - 1) / TB, TB>>>();
    // GCN scatter (1 warp / edge)
    k_gcn_scatter<<<(EE * 32 + TB - 1) / TB, TB>>>(srcE, tgtE);
    // self-loop + bias + ReLU -> g_h
    k_relu<<<(NN * 32 + TB - 1) / TB, TB>>>(bg);
    // q, k, v, skip projections in one kernel (skip writes straight to out)
    gemm4<<<GBLK, TB, SMEM>>>((const float*)p_h,
        Wq, bq, (float*)p_q,
        Wk, bk, (float*)p_k,
        Wv, bv, (float*)p_v,
        Wsk, bsk, out, NN);
    // fused attention: logits + exp + weighted scatter + denom in one pass
    k_attn<<<(EE * 32 + TB - 1) / TB, TB>>>(srcE, tgtE);
    // normalize and add into skip output
    k_combine<<<(NN * 32 + TB - 1) / TB, TB>>>(out);
}

// round 14
// speedup vs baseline: 1.1100x; 1.0956x over previous
#include <cuda_runtime.h>
#include <cuda_bf16.h>
#include <math.h>

// Problem constants (fixed shapes per reference)
#define NN 50000
#define EE 600000
// HID = 128, H = 4, C = 32

// ---------------- scratch (device globals; no allocation allowed) ----------
__device__ float g_h0[NN * 128];     // x @ W_gcn
__device__ float g_h[NN * 128];      // GCN post-ReLU features
__device__ float g_q[NN * 128];
__device__ float g_k[NN * 128];
__device__ float g_v[NN * 128];
__device__ float g_dinv[NN];
__device__ int   g_cnt[NN];          // in-edge count per target (no self loop)
__device__ int   g_row_ptr[NN + 1];  // CSR row pointers (by target)
__device__ int   g_cursor[NN];       // fill cursors
__device__ int   g_esrc[EE];         // source node per edge, grouped by target

// ---------------- f32x2 helpers ---------------------------------------------
__device__ __forceinline__ unsigned long long pack2(float lo, float hi) {
    unsigned long long d;
    asm("mov.b64 %0, {%1, %2};" : "=l"(d) : "f"(lo), "f"(hi));
    return d;
}
__device__ __forceinline__ void unpack2(unsigned long long v, float& lo, float& hi) {
    asm("mov.b64 {%0, %1}, %2;" : "=f"(lo), "=f"(hi) : "l"(v));
}
__device__ __forceinline__ void fma2(unsigned long long& acc, unsigned long long a,
                                     unsigned long long b) {
    asm("fma.rn.f32x2 %0, %1, %2, %0;" : "+l"(acc) : "l"(a), "l"(b));
}

// ---------------- init: zero edge counters -----------------------------------
__global__ void k_zero() {
    int i = blockIdx.x * blockDim.x + threadIdx.x;
    if (i < NN) g_cnt[i] = 0;
}

// ---------------- GEMM: up to 4 weight sets, shared X tile -------------------
// Y_j[n,128] = X[n,128] @ W_j[128,128] (+ b_j).  f32x2 packed FMA.
// 128x128 tile per CTA, 256 threads; X tile stored transposed for row-pair LDS.64.
__global__ __launch_bounds__(256) void gemm4(
    const float* __restrict__ X,
    const float* __restrict__ W0, const float* __restrict__ b0, float* __restrict__ Y0,
    const float* __restrict__ W1, const float* __restrict__ b1, float* __restrict__ Y1,
    const float* __restrict__ W2, const float* __restrict__ b2, float* __restrict__ Y2,
    const float* __restrict__ W3, const float* __restrict__ b3, float* __restrict__ Y3,
    int n)
{
    extern __shared__ float sm[];
    float* Ws  = sm;               // [k][col] 128*128
    float* XsT = sm + 128 * 128;   // [k][row] 128*128
    const int tid  = threadIdx.x;
    const int lane = tid & 31;
    const int wid  = tid >> 5;
    const int row0 = blockIdx.x * 128;
    const int rbase = wid * 16;

    const float4* X4 = (const float4*)X;
    for (int i = tid; i < 128 * 32; i += 256) {
        int r  = i & 127;
        int c4 = i >> 7;
        int row = row0 + r;
        float4 xv = (row < n) ? X4[row * 32 + c4] : make_float4(0.f, 0.f, 0.f, 0.f);
        XsT[(c4 * 4 + 0) * 128 + r] = xv.x;
        XsT[(c4 * 4 + 1) * 128 + r] = xv.y;
        XsT[(c4 * 4 + 2) * 128 + r] = xv.z;
        XsT[(c4 * 4 + 3) * 128 + r] = xv.w;
    }

    const float* Warr[4] = {W0, W1, W2, W3};
    const float* barr[4] = {b0, b1, b2, b3};
    float*       Yarr[4] = {Y0, Y1, Y2, Y3};

    for (int wsel = 0; wsel < 4; wsel++) {
        const float* W = Warr[wsel];
        if (!W) break;
        __syncthreads();
        {
            float4* Ws4 = (float4*)Ws;
            const float4* W4 = (const float4*)W;
            for (int i = tid; i < 128 * 32; i += 256) Ws4[i] = W4[i];
        }
        __syncthreads();

        unsigned long long acc[8][4];
        #pragma unroll
        for (int rp = 0; rp < 8; rp++)
            #pragma unroll
            for (int c = 0; c < 4; c++) acc[rp][c] = 0ull;

        const float4* Ws4 = (const float4*)Ws;
        #pragma unroll 4
        for (int k = 0; k < 128; k++) {
            float4 wv = Ws4[k * 32 + lane];
            unsigned long long wp0 = pack2(wv.x, wv.x);
            unsigned long long wp1 = pack2(wv.y, wv.y);
            unsigned long long wp2 = pack2(wv.z, wv.z);
            unsigned long long wp3 = pack2(wv.w, wv.w);
            const float* xrow = &XsT[k * 128 + rbase];
            #pragma unroll
            for (int rp = 0; rp < 8; rp++) {
                unsigned long long xx =
                    *reinterpret_cast<const unsigned long long*>(xrow + rp * 2);
                fma2(acc[rp][0], xx, wp0);
                fma2(acc[rp][1], xx, wp1);
                fma2(acc[rp][2], xx, wp2);
                fma2(acc[rp][3], xx, wp3);
            }
        }

        const float* b = barr[wsel];
        float4 bv = b ? ((const float4*)b)[lane] : make_float4(0.f, 0.f, 0.f, 0.f);
        float4* Y4 = (float4*)Yarr[wsel];
        #pragma unroll
        for (int rp = 0; rp < 8; rp++) {
            float lo0, hi0, lo1, hi1, lo2, hi2, lo3, hi3;
            unpack2(acc[rp][0], lo0, hi0);
            unpack2(acc[rp][1], lo1, hi1);
            unpack2(acc[rp][2], lo2, hi2);
            unpack2(acc[rp][3], lo3, hi3);
            int row = row0 + rbase + rp * 2;
            if (row < n) {
                float4 o = make_float4(lo0 + bv.x, lo1 + bv.y, lo2 + bv.z, lo3 + bv.w);
                Y4[row * 32 + lane] = o;
            }
            if (row + 1 < n) {
                float4 o = make_float4(hi0 + bv.x, hi1 + bv.y, hi2 + bv.z, hi3 + bv.w);
                Y4[(row + 1) * 32 + lane] = o;
            }
        }
    }
}

// ---------------- CSR construction -------------------------------------------
__global__ void k_deg(const int* __restrict__ tgt) {
    int e = blockIdx.x * blockDim.x + threadIdx.x;
    if (e < EE) atomicAdd(&g_cnt[tgt[e]], 1);
}

// One block, 1024 threads. Exclusive scan of g_cnt -> row_ptr, cursor.
__global__ __launch_bounds__(1024) void k_scan() {
    __shared__ int sums[1024];
    const int tid = threadIdx.x;
    const int CH = (NN + 1023) / 1024;   // 49
    int beg = tid * CH;
    int end = min(beg + CH, NN);
    int s = 0;
    for (int i = beg; i < end; i++) s += g_cnt[i];
    sums[tid] = s;
    __syncthreads();
    // Hillis-Steele inclusive scan
    for (int off = 1; off < 1024; off <<= 1) {
        int v = 0;
        if (tid >= off) v = sums[tid - off];
        __syncthreads();
        if (tid >= off) sums[tid] += v;
        __syncthreads();
    }
    int run = (tid > 0) ? sums[tid - 1] : 0;
    for (int i = beg; i < end; i++) {
        g_row_ptr[i] = run;
        g_cursor[i]  = run;
        run += g_cnt[i];
    }
    if (tid == 0) g_row_ptr[NN] = EE;
}

__global__ void k_fill(const int* __restrict__ src, const int* __restrict__ tgt) {
    int e = blockIdx.x * blockDim.x + threadIdx.x;
    if (e < EE) {
        int t = tgt[e];
        int pos = atomicAdd(&g_cursor[t], 1);
        g_esrc[pos] = src[e];
    }
}

__global__ void k_dinv() {
    int i = blockIdx.x * blockDim.x + threadIdx.x;
    if (i < NN) g_dinv[i] = rsqrtf((float)(g_cnt[i] + 1));  // +1 self loop
}

// ---------------- GCN aggregate (warp per target, gather) --------------------
// h[t] = relu( dinv[t] * sum_s dinv[s]*h0[s]  +  dinv[t]^2 * h0[t] + b )
__global__ __launch_bounds__(256) void k_gcn_agg(const float* __restrict__ b_gcn) {
    int t = (blockIdx.x * blockDim.x + threadIdx.x) >> 5;
    if (t >= NN) return;
    const int lane = threadIdx.x & 31;
    const int beg = g_row_ptr[t];
    const int end = g_row_ptr[t + 1];
    const float4* h04 = (const float4*)g_h0;

    float4 acc = make_float4(0.f, 0.f, 0.f, 0.f);
    for (int base = beg; base < end; base += 32) {
        int nloc = min(32, end - base);
        int sj = (base + lane < end) ? g_esrc[base + lane] : 0;
        float dj = (base + lane < end) ? g_dinv[sj] : 0.f;
        for (int j = 0; j < nloc; j++) {
            int s = __shfl_sync(0xffffffffu, sj, j);
            float ds = __shfl_sync(0xffffffffu, dj, j);
            float4 hv = h04[s * 32 + lane];
            acc.x = fmaf(ds, hv.x, acc.x);
            acc.y = fmaf(ds, hv.y, acc.y);
            acc.z = fmaf(ds, hv.z, acc.z);
            acc.w = fmaf(ds, hv.w, acc.w);
        }
    }
    float dt = g_dinv[t];
    float sw = dt * dt;
    float4 h0v = h04[t * 32 + lane];
    float4 bv = ((const float4*)b_gcn)[lane];
    float4 o;
    o.x = fmaxf(fmaf(acc.x, dt, fmaf(h0v.x, sw, bv.x)), 0.f);
    o.y = fmaxf(fmaf(acc.y, dt, fmaf(h0v.y, sw, bv.y)), 0.f);
    o.z = fmaxf(fmaf(acc.z, dt, fmaf(h0v.z, sw, bv.z)), 0.f);
    o.w = fmaxf(fmaf(acc.w, dt, fmaf(h0v.w, sw, bv.w)), 0.f);
    ((float4*)g_h)[t * 32 + lane] = o;
}

// ---------------- attention (warp per target, gather) ------------------------
// For each target t: load q[t] once; per incident edge gather k[s], v[s];
// ea = exp(q.k/sqrt(C)) per head (no max subtraction needed; logits are O(1));
// accumulate ea*v and ea; finally out[t] += acc/den.
__global__ __launch_bounds__(256) void k_attn(float* __restrict__ out) {
    int t = (blockIdx.x * blockDim.x + threadIdx.x) >> 5;
    if (t >= NN) return;
    const int lane = threadIdx.x & 31;
    const int beg = g_row_ptr[t];
    const int end = g_row_ptr[t + 1];
    if (beg == end) return;   // no edges: out keeps skip-GEMM value

    const float4* q4 = (const float4*)g_q;
    const float4* k4 = (const float4*)g_k;
    const float4* v4 = (const float4*)g_v;

    float4 qv = q4[t * 32 + lane];
    float4 acc = make_float4(0.f, 0.f, 0.f, 0.f);
    float den = 0.f;

    for (int base = beg; base < end; base += 32) {
        int nloc = min(32, end - base);
        int sj = (base + lane < end) ? g_esrc[base + lane] : 0;
        for (int j = 0; j < nloc; j++) {
            int s = __shfl_sync(0xffffffffu, sj, j);
            float4 kv = k4[s * 32 + lane];
            float4 vv = v4[s * 32 + lane];
            float p = qv.x * kv.x + qv.y * kv.y + qv.z * kv.z + qv.w * kv.w;
            // reduce within 8-lane groups (one head = 32 cols = 8 float4 lanes)
            p += __shfl_xor_sync(0xffffffffu, p, 1);
            p += __shfl_xor_sync(0xffffffffu, p, 2);
            p += __shfl_xor_sync(0xffffffffu, p, 4);
            float ea = __expf(p * 0.17677669529663687f);  // 1/sqrt(32)
            acc.x = fmaf(ea, vv.x, acc.x);
            acc.y = fmaf(ea, vv.y, acc.y);
            acc.z = fmaf(ea, vv.z, acc.z);
            acc.w = fmaf(ea, vv.w, acc.w);
            den += ea;
        }
    }
    float inv = (den > 0.f) ? (1.0f / den) : 0.f;
    float4 o = ((float4*)out)[t * 32 + lane];
    o.x = fmaf(acc.x, inv, o.x);
    o.y = fmaf(acc.y, inv, o.y);
    o.z = fmaf(acc.z, inv, o.z);
    o.w = fmaf(acc.w, inv, o.w);
    ((float4*)out)[t * 32 + lane] = o;
}

// ---------------- launch -----------------------------------------------------
extern "C" void kernel_launch(void* const* d_in, const int* in_sizes, int n_in,
                              void* d_out, int out_size) {
    const float* x  = (const float*)d_in[0];
    const int*   ei = (const int*)d_in[1];
    const int* srcE = ei;        // edge_index[0]
    const int* tgtE = ei + EE;   // edge_index[1]
    const float* Wg = (const float*)d_in[2];
    const float* bg = (const float*)d_in[3];
    const float* Wq = (const float*)d_in[4];
    const float* bq = (const float*)d_in[5];
    const float* Wk = (const float*)d_in[6];
    const float* bk = (const float*)d_in[7];
    const float* Wv = (const float*)d_in[8];
    const float* bv = (const float*)d_in[9];
    const float* Wsk = (const float*)d_in[10];
    const float* bsk = (const float*)d_in[11];
    float* out = (float*)d_out;

    void *p_h0, *p_h, *p_q, *p_k, *p_v;
    cudaGetSymbolAddress(&p_h0, g_h0);
    cudaGetSymbolAddress(&p_h,  g_h);
    cudaGetSymbolAddress(&p_q,  g_q);
    cudaGetSymbolAddress(&p_k,  g_k);
    cudaGetSymbolAddress(&p_v,  g_v);

    const int SMEM = 2 * 128 * 128 * (int)sizeof(float);   // 128KB
    cudaFuncSetAttribute(gemm4, cudaFuncAttributeMaxDynamicSharedMemorySize, SMEM);

    const int TB = 256;
    const int GBLK = (NN + 127) / 128;
    const int NODE_WARP_GRID = (NN * 32 + TB - 1) / TB;

    // CSR build
    k_zero<<<(NN + TB - 1) / TB, TB>>>();
    k_deg<<<(EE + TB - 1) / TB, TB>>>(tgtE);
    k_scan<<<1, 1024>>>();
    k_fill<<<(EE + TB - 1) / TB, TB>>>(srcE, tgtE);
    k_dinv<<<(NN + TB - 1) / TB, TB>>>();
    // h0 = x @ W_gcn
    gemm4<<<GBLK, TB, SMEM>>>(x,
        Wg, nullptr, (float*)p_h0,
        nullptr, nullptr, nullptr,
        nullptr, nullptr, nullptr,
        nullptr, nullptr, nullptr, NN);
    // GCN aggregate + self loop + bias + ReLU (gather, no atomics)
    k_gcn_agg<<<NODE_WARP_GRID, TB>>>(bg);
    // q, k, v, skip projections in one kernel (skip writes straight to out)
    gemm4<<<GBLK, TB, SMEM>>>((const float*)p_h,
        Wq, bq, (float*)p_q,
        Wk, bk, (float*)p_k,
        Wv, bv, (float*)p_v,
        Wsk, bsk, out, NN);
    // attention gather (no atomics)
    k_attn<<<NODE_WARP_GRID, TB>>>(out);
}